// round 17
// baseline (speedup 1.0000x reference)
#include <cuda_runtime.h>
#include <cuda_fp16.h>
#include <math.h>
#include <stdint.h>

// Problem constants
#define NN   10000
#define EE   160000
#define ETOT 170000          // edges + self loops
#define FIN  256
#define HID  128
#define H1N  5
#define D1   640             // H1N*HID
#define H3N  3
#define D3   384             // H3N*HID
#define NCLS 10
#define NG   64
#define NEG_SLOPE 0.2f
#define CUT  5056            // node split for layer-boundary pipelining (79*64)

// ---------------- scratch (static device globals; no allocation) ------------
__device__ __half g_h16a[NN * D1];   // layer 1 & 3 projected features (fp16)
__device__ __half g_h16b[NN * D1];   // layer 2 projected features (fp16)
__device__ float g_x1  [NN * D1];
__device__ float g_x2  [NN * D1];
__device__ float g_alsa[NN * H1N];
__device__ float g_alda[NN * H1N];
__device__ float g_alsb[NN * H1N];
__device__ float g_aldb[NN * H1N];
__device__ int   g_rowstart[NN + 1];
__device__ int   g_cursor  [NN];
__device__ int   g_csrsrc  [ETOT];
__device__ float g_pool[NG * HID];
__device__ float g_cnt [NG];
// fp16 operands: activations and weights single fp16
__device__ __half g_A16[NN * D1];
__device__ __half g_B1 [D1 * FIN];
__device__ __half g_B2 [D1 * D1];
__device__ __half g_B3 [D3 * D1];

// ---------------- CSR build -------------------------------------------------
__global__ void k_zero_cursor() {
    int i = blockIdx.x * blockDim.x + threadIdx.x;
    if (i < NN) g_cursor[i] = 0;
}

__global__ void k_count(const int* __restrict__ dst) {
    int e = blockIdx.x * blockDim.x + threadIdx.x;
    if (e < ETOT) {
        int d = (e < EE) ? dst[e] : (e - EE);
        atomicAdd(&g_cursor[d], 1);
    }
}

__global__ void k_scan() {
    __shared__ int partial[1024];
    const int t = threadIdx.x;
    const int CHUNK = (NN + 1023) / 1024;
    int base = t * CHUNK;
    int sum = 0;
    for (int i = 0; i < CHUNK; i++) {
        int idx = base + i;
        if (idx < NN) sum += g_cursor[idx];
    }
    partial[t] = sum;
    __syncthreads();
    for (int off = 1; off < 1024; off <<= 1) {
        int v = (t >= off) ? partial[t - off] : 0;
        __syncthreads();
        partial[t] += v;
        __syncthreads();
    }
    int run = (t == 0) ? 0 : partial[t - 1];
    for (int i = 0; i < CHUNK; i++) {
        int idx = base + i;
        if (idx < NN) {
            int c = g_cursor[idx];
            g_rowstart[idx] = run;
            g_cursor[idx]   = run;
            run += c;
        }
    }
    if (t == 1023) g_rowstart[NN] = partial[1023];
}

__global__ void k_scatter(const int* __restrict__ src, const int* __restrict__ dst) {
    int e = blockIdx.x * blockDim.x + threadIdx.x;
    if (e < ETOT) {
        int s = (e < EE) ? src[e] : (e - EE);
        int d = (e < EE) ? dst[e] : (e - EE);
        int pos = atomicAdd(&g_cursor[d], 1);
        g_csrsrc[pos] = s;
    }
}

// ---------------- fp16 conversions ------------------------------------------
__global__ void k_convA(const float* __restrict__ A, int len) {
    int i = blockIdx.x * blockDim.x + threadIdx.x;
    if (i < len) g_A16[i] = __float2half_rn(A[i]);
}

// W [K,N] row-major -> B [N,K] K-major fp16, coalesced via 32x32 smem tile
__global__ void k_convWt(const float* __restrict__ W, __half* __restrict__ B,
                         int K, int N) {
    __shared__ float t[32][33];
    const int nb = blockIdx.x * 32, kb = blockIdx.y * 32;
    const int tx = threadIdx.x, ty = threadIdx.y;   // 32 x 8
#pragma unroll
    for (int i = ty; i < 32; i += 8) {
        int k = kb + i, n = nb + tx;
        if (k < K && n < N) t[i][tx] = W[(size_t)k * N + n];
    }
    __syncthreads();
#pragma unroll
    for (int i = ty; i < 32; i += 8) {
        int n = nb + i, k = kb + tx;
        if (k < K && n < N) B[(size_t)n * K + k] = __float2half_rn(t[tx][i]);
    }
}

// ---------------- cp.async / ldmatrix helpers -------------------------------
__device__ __forceinline__ void cp16(uint32_t saddr, const void* gptr, int szbytes) {
    asm volatile("cp.async.cg.shared.global [%0], [%1], 16, %2;"
                 :: "r"(saddr), "l"(gptr), "r"(szbytes) : "memory");
}
#define CP_COMMIT() asm volatile("cp.async.commit_group;" ::: "memory")
#define CP_WAIT2()  asm volatile("cp.async.wait_group 2;" ::: "memory")
#define CP_WAIT1()  asm volatile("cp.async.wait_group 1;" ::: "memory")
#define CP_WAIT0()  asm volatile("cp.async.wait_group 0;" ::: "memory")

__device__ __forceinline__ void ldsm4(uint32_t* r, uint32_t saddr) {
    asm volatile("ldmatrix.sync.aligned.m8n8.x4.shared.b16 {%0,%1,%2,%3}, [%4];"
                 : "=r"(r[0]), "=r"(r[1]), "=r"(r[2]), "=r"(r[3]) : "r"(saddr));
}

// ---------------- warp-mma fp16 GEMM (BM=64, 3-stage pipeline) --------------
#define BM 64
#define BK 32
#define SSTR 40
#define AT_B (BM * SSTR * 2)
#define BT_B (128 * SSTR * 2)
#define ST_A  0
#define ST_B  (AT_B)
#define STAGE_B (AT_B + BT_B)
#define NSTAGE 3
#define GSMEM_TOTAL (NSTAGE * STAGE_B)

__device__ __forceinline__ void mma16816(float* c, const uint32_t* a,
                                         uint32_t b0, uint32_t b1) {
    asm volatile(
        "mma.sync.aligned.m16n8k16.row.col.f32.f16.f16.f32 "
        "{%0,%1,%2,%3}, {%4,%5,%6,%7}, {%8,%9}, {%0,%1,%2,%3};"
        : "+f"(c[0]), "+f"(c[1]), "+f"(c[2]), "+f"(c[3])
        : "r"(a[0]), "r"(a[1]), "r"(a[2]), "r"(a[3]), "r"(b0), "r"(b1));
}

__global__ void __launch_bounds__(256, 3)
k_gemm_mma(const __half* __restrict__ A16, const __half* __restrict__ B16,
           __half* __restrict__ C16,
           const float* __restrict__ a_s, const float* __restrict__ a_d,
           float* __restrict__ als, float* __restrict__ ald,
           int m0, int M, int Nn, int K, int H) {
    extern __shared__ char sm[];
    __shared__ float sAls[BM];
    __shared__ float sAld[BM];
    const uint32_t sb = (uint32_t)__cvta_generic_to_shared(sm);
    const int tid = threadIdx.x;
    const int wid = tid >> 5;
    const int lane = tid & 31;
    const int g  = lane >> 2;
    const int t4 = lane & 3;
    const int warp_m = wid & 1;
    const int warp_n = wid >> 1;
    const int head = blockIdx.x;
    const int bm = m0 + (blockIdx.y << 6);
    const int bn = head << 7;

    const int a_row = ((lane >> 3) & 1) * 8 + (lane & 7);
    const int a_kof = (lane >> 4) * 8;
    const int b_row = ((lane >> 4) & 1) * 8 + (lane & 7);
    const int b_kof = ((lane >> 3) & 1) * 8;

    float acc[2][4][4];
#pragma unroll
    for (int mi = 0; mi < 2; mi++)
#pragma unroll
        for (int ni = 0; ni < 4; ni++)
#pragma unroll
            for (int j = 0; j < 4; j++) acc[mi][ni][j] = 0.f;

    const int niter = K / BK;

    auto fill = [&](int k0, int buf) {
        uint32_t st = sb + buf * STAGE_B;
        {
            int row = tid >> 2, s = tid & 3;
            uint32_t soff = row * (SSTR * 2) + s * 16;
            int grow = bm + row;
            int asz  = (grow < M) ? 16 : 0;
            int arow = (grow < M) ? grow : 0;
            cp16(st + ST_A + soff, A16 + (size_t)arow * K + k0 + s * 8, asz);
        }
#pragma unroll
        for (int i = 0; i < 2; i++) {
            int seg = tid + (i << 8);
            int row = seg >> 2, s = seg & 3;
            uint32_t soff = row * (SSTR * 2) + s * 16;
            int brow = bn + row;
            cp16(st + ST_B + soff, B16 + (size_t)brow * K + k0 + s * 8, 16);
        }
    };

    fill(0, 0);
    CP_COMMIT();
    if (niter > 1) { fill(BK, 1); CP_COMMIT(); }

    for (int it = 0; it < niter; it++) {
        if (it + 2 < niter) {
            fill((it + 2) * BK, (it + 2) % NSTAGE);
            CP_COMMIT();
            CP_WAIT2();
        } else if (it + 1 < niter) {
            CP_WAIT1();
        } else {
            CP_WAIT0();
        }
        __syncthreads();

        const uint32_t st = sb + (it % NSTAGE) * STAGE_B;

#pragma unroll
        for (int kk = 0; kk < BK; kk += 16) {
            uint32_t af[2][4];
#pragma unroll
            for (int mi = 0; mi < 2; mi++) {
                uint32_t off = ((warp_m * 32 + mi * 16 + a_row) * SSTR + kk + a_kof) * 2;
                ldsm4(af[mi], st + ST_A + off);
            }
            uint32_t bf[2][4];
#pragma unroll
            for (int qi = 0; qi < 2; qi++) {
                uint32_t off = ((warp_n * 32 + qi * 16 + b_row) * SSTR + kk + b_kof) * 2;
                ldsm4(bf[qi], st + ST_B + off);
            }
#pragma unroll
            for (int qi = 0; qi < 2; qi++) {
#pragma unroll
                for (int half = 0; half < 2; half++) {
                    int ni = qi * 2 + half;
                    uint32_t h0 = bf[qi][half * 2], h1 = bf[qi][half * 2 + 1];
#pragma unroll
                    for (int mi = 0; mi < 2; mi++) {
                        mma16816(acc[mi][ni], af[mi], h0, h1);
                    }
                }
            }
        }
        __syncthreads();
    }

    float asv[4][2], adv[4][2];
#pragma unroll
    for (int ni = 0; ni < 4; ni++) {
#pragma unroll
        for (int j = 0; j < 2; j++) {
            int col = head * HID + warp_n * 32 + ni * 8 + t4 * 2 + j;
            asv[ni][j] = a_s[col];
            adv[ni][j] = a_d[col];
        }
    }

    if (tid < BM) { sAls[tid] = 0.f; sAld[tid] = 0.f; }
    __syncthreads();

#pragma unroll
    for (int mi = 0; mi < 2; mi++) {
        int lr0 = warp_m * 32 + mi * 16 + g;
        int lr1 = lr0 + 8;
        int r0 = bm + lr0;
        int r1 = bm + lr1;
        float ps0 = 0.f, pd0 = 0.f, ps1 = 0.f, pd1 = 0.f;
#pragma unroll
        for (int ni = 0; ni < 4; ni++) {
            int col = bn + warp_n * 32 + ni * 8 + t4 * 2;
            if (r0 < M)
                *(__half2*)(C16 + (size_t)r0 * Nn + col) =
                    __floats2half2_rn(acc[mi][ni][0], acc[mi][ni][1]);
            if (r1 < M)
                *(__half2*)(C16 + (size_t)r1 * Nn + col) =
                    __floats2half2_rn(acc[mi][ni][2], acc[mi][ni][3]);
            ps0 += acc[mi][ni][0] * asv[ni][0] + acc[mi][ni][1] * asv[ni][1];
            pd0 += acc[mi][ni][0] * adv[ni][0] + acc[mi][ni][1] * adv[ni][1];
            ps1 += acc[mi][ni][2] * asv[ni][0] + acc[mi][ni][3] * asv[ni][1];
            pd1 += acc[mi][ni][2] * adv[ni][0] + acc[mi][ni][3] * adv[ni][1];
        }
#pragma unroll
        for (int o = 1; o <= 2; o <<= 1) {
            ps0 += __shfl_xor_sync(0xffffffffu, ps0, o);
            pd0 += __shfl_xor_sync(0xffffffffu, pd0, o);
            ps1 += __shfl_xor_sync(0xffffffffu, ps1, o);
            pd1 += __shfl_xor_sync(0xffffffffu, pd1, o);
        }
        if (t4 == 0) {
            atomicAdd(&sAls[lr0], ps0);
            atomicAdd(&sAld[lr0], pd0);
            atomicAdd(&sAls[lr1], ps1);
            atomicAdd(&sAld[lr1], pd1);
        }
    }
    __syncthreads();
    if (tid < BM) {
        int r = bm + tid;
        if (r < M) {
            als[r * H + head] = sAls[tid];
            ald[r * H + head] = sAld[tid];
        }
    }
}

// ---------------- warp-per-(dst,head) softmax aggregation (no max shift) ----
__device__ __forceinline__ float elu_f(float v) { return v > 0.f ? v : expm1f(v); }

// MODE 1: xout = elu(v+bias) + fp16 A16 store; MODE 2: +residual
template <int MODE>
__global__ void __launch_bounds__(256)
k_aggw(const __half* __restrict__ h16, const float* __restrict__ als,
       const float* __restrict__ ald,
       const float* __restrict__ bias, const float* __restrict__ xprev,
       float* __restrict__ xout, __half* __restrict__ A16,
       int idx0, int idxN, int H) {
    const int idx = idx0 + blockIdx.x * 8 + (threadIdx.x >> 5);
    if (idx >= idxN) return;
    const int n = idx / H, head = idx - n * H;
    const int lane = threadIdx.x & 31;
    const int D = H * HID;
    const int rs = g_rowstart[n], re = g_rowstart[n + 1];
    const float ad = ald[idx];

    float s = 0.f;
    float ax = 0.f, ay = 0.f, az = 0.f, aw = 0.f;
    const __half* hbase = h16 + head * HID + lane * 4;

    for (int base = rs; base < re; base += 32) {
        int cnt = re - base; if (cnt > 32) cnt = 32;
        float e = 0.f; int sc = 0;
        if (lane < cnt) {
            sc = g_csrsrc[base + lane];
            float l = als[sc * H + head] + ad;
            l = (l > 0.f) ? l : NEG_SLOPE * l;
            e = __expf(l);
        }
        float es = e;
#pragma unroll
        for (int o = 16; o > 0; o >>= 1)
            es += __shfl_xor_sync(0xffffffffu, es, o);
        s += es;
#pragma unroll 4
        for (int j = 0; j < cnt; j++) {
            float aj = __shfl_sync(0xffffffffu, e, j);
            int  sj  = __shfl_sync(0xffffffffu, sc, j);
            uint2 hv = *(const uint2*)(hbase + (size_t)sj * D);
            float2 f01 = __half22float2(*(const __half2*)&hv.x);
            float2 f23 = __half22float2(*(const __half2*)&hv.y);
            ax += aj * f01.x; ay += aj * f01.y; az += aj * f23.x; aw += aj * f23.y;
        }
    }
    float inv = 1.f / (s + 1e-16f);
    float4 v = make_float4(ax * inv, ay * inv, az * inv, aw * inv);

    const int colbase = head * HID + lane * 4;
    const size_t gidx = (size_t)n * D + colbase;
    float4 b4 = *(const float4*)(bias + colbase);
    float4 w = make_float4(v.x + b4.x, v.y + b4.y, v.z + b4.z, v.w + b4.w);
    if (MODE == 2) {
        float4 p4 = *(const float4*)(xprev + gidx);
        w.x += p4.x; w.y += p4.y; w.z += p4.z; w.w += p4.w;
    }
    w.x = elu_f(w.x); w.y = elu_f(w.y); w.z = elu_f(w.z); w.w = elu_f(w.w);
    *(float4*)(xout + gidx) = w;
    __half2* p16 = (__half2*)(A16 + gidx);
    p16[0] = __floats2half2_rn(w.x, w.y);
    p16[1] = __floats2half2_rn(w.z, w.w);
}

// ---------------- fused layer-3 agg + head-mean + bias + pool ---------------
// One warp per node; loops the 3 heads, then atomicAdds into the pool sums.
__global__ void __launch_bounds__(256)
k_aggpool(const __half* __restrict__ h16, const float* __restrict__ als,
          const float* __restrict__ ald, const float* __restrict__ b3,
          const int* __restrict__ batch) {
    const int n = blockIdx.x * 8 + (threadIdx.x >> 5);
    if (n >= NN) return;
    const int lane = threadIdx.x & 31;
    const int rs = g_rowstart[n], re = g_rowstart[n + 1];

    float mx = 0.f, my = 0.f, mz = 0.f, mw = 0.f;
#pragma unroll
    for (int head = 0; head < H3N; head++) {
        const float ad = ald[n * H3N + head];
        const __half* hbase = h16 + head * HID + lane * 4;
        float s = 0.f, ax = 0.f, ay = 0.f, az = 0.f, aw = 0.f;
        for (int base = rs; base < re; base += 32) {
            int cnt = re - base; if (cnt > 32) cnt = 32;
            float e = 0.f; int sc = 0;
            if (lane < cnt) {
                sc = g_csrsrc[base + lane];
                float l = als[sc * H3N + head] + ad;
                l = (l > 0.f) ? l : NEG_SLOPE * l;
                e = __expf(l);
            }
            float es = e;
#pragma unroll
            for (int o = 16; o > 0; o >>= 1)
                es += __shfl_xor_sync(0xffffffffu, es, o);
            s += es;
#pragma unroll 4
            for (int j = 0; j < cnt; j++) {
                float aj = __shfl_sync(0xffffffffu, e, j);
                int  sj  = __shfl_sync(0xffffffffu, sc, j);
                uint2 hv = *(const uint2*)(hbase + (size_t)sj * D3);
                float2 f01 = __half22float2(*(const __half2*)&hv.x);
                float2 f23 = __half22float2(*(const __half2*)&hv.y);
                ax += aj * f01.x; ay += aj * f01.y; az += aj * f23.x; aw += aj * f23.y;
            }
        }
        float inv = 1.f / (s + 1e-16f);
        mx += ax * inv; my += ay * inv; mz += az * inv; mw += aw * inv;
    }
    const int c = lane * 4;
    float4 b4 = *(const float4*)(b3 + c);
    int grp = batch[n];
    atomicAdd(&g_pool[grp * HID + c + 0], mx * (1.f / 3.f) + b4.x);
    atomicAdd(&g_pool[grp * HID + c + 1], my * (1.f / 3.f) + b4.y);
    atomicAdd(&g_pool[grp * HID + c + 2], mz * (1.f / 3.f) + b4.z);
    atomicAdd(&g_pool[grp * HID + c + 3], mw * (1.f / 3.f) + b4.w);
    if (lane == 0) atomicAdd(&g_cnt[grp], 1.0f);
}

// ---------------- pooling zero + classifier head ----------------------------
__global__ void k_zero_pool() {
    int i = blockIdx.x * blockDim.x + threadIdx.x;
    if (i < NG * HID) g_pool[i] = 0.f;
    if (i < NG) g_cnt[i] = 0.f;
}

__global__ void k_head(const float* __restrict__ Wc, const float* __restrict__ bc,
                       float* __restrict__ out, int out_size) {
    int g = blockIdx.x, t = threadIdx.x;
    __shared__ float sp[HID];
    __shared__ float lg[NCLS];
    float invc = 1.0f / fmaxf(g_cnt[g], 1.0f);
    sp[t] = g_pool[g * HID + t] * invc;
    __syncthreads();
    if (t < NCLS) {
        float a = bc[t];
#pragma unroll
        for (int c = 0; c < HID; c++) a += sp[c] * Wc[c * NCLS + t];
        lg[t] = a;
    }
    __syncthreads();
    if (t == 0) {
        float m = lg[0];
        for (int k = 1; k < NCLS; k++) m = fmaxf(m, lg[k]);
        float s = 0.f;
        for (int k = 0; k < NCLS; k++) s += expf(lg[k] - m);
        float lse = m + logf(s);
        for (int k = 0; k < NCLS; k++) {
            int i1 = g * NCLS + k;
            int i2 = NG * NCLS + g * NCLS + k;
            if (i1 < out_size) out[i1] = lg[k];
            if (i2 < out_size) out[i2] = lg[k] - lse;
        }
    }
}

// NOTE on k_aggpool mean+bias: the reference computes pooled = mean_g(x3),
// x3 = mean_heads(v) + b3. Adding b3 per node then averaging by count is
// identical to adding b3 after the mean (b3 constant per channel).

// ---------------- launch ----------------------------------------------------
extern "C" void kernel_launch(void* const* d_in, const int* in_sizes, int n_in,
                              void* d_out, int out_size) {
    const float* x    = (const float*)d_in[0];
    const int*   ei   = (const int*)  d_in[1];
    const int*   batch= (const int*)  d_in[2];
    const float* W1   = (const float*)d_in[3];
    const float* a1s  = (const float*)d_in[4];
    const float* a1d  = (const float*)d_in[5];
    const float* b1   = (const float*)d_in[6];
    const float* W2   = (const float*)d_in[7];
    const float* a2s  = (const float*)d_in[8];
    const float* a2d  = (const float*)d_in[9];
    const float* b2   = (const float*)d_in[10];
    const float* W3   = (const float*)d_in[11];
    const float* a3s  = (const float*)d_in[12];
    const float* a3d  = (const float*)d_in[13];
    const float* b3   = (const float*)d_in[14];
    const float* Wc   = (const float*)d_in[15];
    const float* bc   = (const float*)d_in[16];
    float* out = (float*)d_out;

    const int* srcp = ei;
    const int* dstp = ei + EE;

    float *p_x1, *p_x2, *p_alsa, *p_alda, *p_alsb, *p_aldb;
    __half *p_ha, *p_hb, *p_A16, *p_B1, *p_B2, *p_B3;
    cudaGetSymbolAddress((void**)&p_ha,   g_h16a);
    cudaGetSymbolAddress((void**)&p_hb,   g_h16b);
    cudaGetSymbolAddress((void**)&p_x1,   g_x1);
    cudaGetSymbolAddress((void**)&p_x2,   g_x2);
    cudaGetSymbolAddress((void**)&p_alsa, g_alsa);
    cudaGetSymbolAddress((void**)&p_alda, g_alda);
    cudaGetSymbolAddress((void**)&p_alsb, g_alsb);
    cudaGetSymbolAddress((void**)&p_aldb, g_aldb);
    cudaGetSymbolAddress((void**)&p_A16,  g_A16);
    cudaGetSymbolAddress((void**)&p_B1,   g_B1);
    cudaGetSymbolAddress((void**)&p_B2,   g_B2);
    cudaGetSymbolAddress((void**)&p_B3,   g_B3);

    cudaFuncSetAttribute(k_gemm_mma, cudaFuncAttributeMaxDynamicSharedMemorySize,
                         GSMEM_TOTAL);

    static cudaStream_t side = nullptr;
    static cudaEvent_t ev[8];
    if (side == nullptr) {
        cudaStreamCreateWithFlags(&side, cudaStreamNonBlocking);
        for (int i = 0; i < 8; i++)
            cudaEventCreateWithFlags(&ev[i], cudaEventDisableTiming);
    }

    const int MTA = CUT / 64;              // 79  (rows 0..CUT-1)
    const int MTB = (NN - CUT + 63) / 64;  // 78  (rows CUT..NN-1)
    const int A1cut = (CUT * H1N + 7) / 8;
    const int A1rem = ((NN - CUT) * H1N + 7) / 8;
    dim3 tb(32, 8);

    // ---- fork: side branch does CSR build + convW2/convW3 + pool zero ----
    cudaEventRecord(ev[0], 0);
    cudaStreamWaitEvent(side, ev[0], 0);
    k_zero_cursor<<<(NN + 255) / 256, 256, 0, side>>>();
    k_count<<<(ETOT + 255) / 256, 256, 0, side>>>(dstp);
    k_scan<<<1, 1024, 0, side>>>();
    k_scatter<<<(ETOT + 255) / 256, 256, 0, side>>>(srcp, dstp);
    k_convWt<<<dim3(D1 / 32, D1 / 32), tb, 0, side>>>(W2, p_B2, D1, D1);
    k_convWt<<<dim3(D3 / 32, D1 / 32), tb, 0, side>>>(W3, p_B3, D1, D3);
    k_zero_pool<<<(NG * HID + 255) / 256, 256, 0, side>>>();
    cudaEventRecord(ev[1], side);

    // ---- main critical path ----
    k_convWt<<<dim3(D1 / 32, FIN / 32), tb>>>(W1, p_B1, FIN, D1);
    k_convA<<<(NN * FIN + 255) / 256, 256>>>(x, NN * FIN);

    // Layer 1 GEMM (full, main) -> h_a, als_a
    k_gemm_mma<<<dim3(H1N, MTA + MTB), 256, GSMEM_TOTAL>>>(p_A16, p_B1,
        p_ha, a1s, a1d, p_alsa, p_alda, 0, NN, D1, FIN, H1N);

    cudaStreamWaitEvent(0, ev[1], 0);   // CSR + convW2/3 ready

    // ---- boundary 1->2: agg1_A ; [gemm2_A || agg1_B] ; gemm2_B ----
    k_aggw<1><<<A1cut, 256>>>(p_ha, p_alsa, p_alda, b1, nullptr, p_x1, p_A16,
                              0, CUT * H1N, H1N);
    cudaEventRecord(ev[2], 0);
    cudaStreamWaitEvent(side, ev[2], 0);
    k_gemm_mma<<<dim3(H1N, MTA), 256, GSMEM_TOTAL, side>>>(p_A16, p_B2,
        p_hb, a2s, a2d, p_alsb, p_aldb, 0, NN, D1, D1, H1N);
    k_aggw<1><<<A1rem, 256>>>(p_ha, p_alsa, p_alda, b1, nullptr, p_x1, p_A16,
                              CUT * H1N, NN * H1N, H1N);
    cudaEventRecord(ev[3], 0);
    cudaStreamWaitEvent(side, ev[3], 0);
    k_gemm_mma<<<dim3(H1N, MTB), 256, GSMEM_TOTAL, side>>>(p_A16, p_B2,
        p_hb, a2s, a2d, p_alsb, p_aldb, CUT, NN, D1, D1, H1N);
    cudaEventRecord(ev[4], side);

    // ---- boundary 2->3: agg2_A ; [gemm3_A || agg2_B] ; gemm3_B ----
    cudaStreamWaitEvent(0, ev[4], 0);
    k_aggw<2><<<A1cut, 256>>>(p_hb, p_alsb, p_aldb, b2, p_x1, p_x2, p_A16,
                              0, CUT * H1N, H1N);
    cudaEventRecord(ev[5], 0);
    cudaStreamWaitEvent(side, ev[5], 0);
    k_gemm_mma<<<dim3(H3N, MTA), 256, GSMEM_TOTAL, side>>>(p_A16, p_B3,
        p_ha, a3s, a3d, p_alsa, p_alda, 0, NN, D3, D1, H3N);
    k_aggw<2><<<A1rem, 256>>>(p_hb, p_alsb, p_aldb, b2, p_x1, p_x2, p_A16,
                              CUT * H1N, NN * H1N, H1N);
    cudaEventRecord(ev[6], 0);
    cudaStreamWaitEvent(side, ev[6], 0);
    k_gemm_mma<<<dim3(H3N, MTB), 256, GSMEM_TOTAL, side>>>(p_A16, p_B3,
        p_ha, a3s, a3d, p_alsa, p_alda, CUT, NN, D3, D1, H3N);
    cudaEventRecord(ev[7], side);

    // ---- layer 3 fused agg+mean+bias+pool, then head ----
    cudaStreamWaitEvent(0, ev[7], 0);
    k_aggpool<<<(NN + 7) / 8, 256>>>(p_ha, p_alsa, p_alda, b3, batch);
    k_head<<<NG, 128>>>(Wc, bc, out, out_size);
}